// round 3
// baseline (speedup 1.0000x reference)
#include <cuda_runtime.h>
#include <cstdint>
#include <cstddef>

#define S_    128
#define B_    64
#define V_    32000
#define E_    32
#define H_    16
#define ROWS  (S_ * B_)        // 8192
#define VCHUNK 6400
#define NCHUNK 5

typedef unsigned long long ull;

// ---------------- device scratch (no allocations allowed) ----------------
__device__ float g_xw[ROWS * H_];      // X @ Wx, per (s,b) row       (512 KB)
__device__ ull   g_hdup[ROWS * H_];    // h duplicated as (h,h) f32x2 (1 MB)
__device__ float g_part[NCHUNK * ROWS];
__device__ float g_lse[ROWS];

// ---------------- f32x2 helpers (Blackwell packed fp32) ----------------
__device__ __forceinline__ ull ffma2(ull a, ull b, ull c) {
    ull d; asm("fma.rn.f32x2 %0, %1, %2, %3;" : "=l"(d) : "l"(a), "l"(b), "l"(c));
    return d;
}
__device__ __forceinline__ ull fadd2(ull a, ull b) {
    ull d; asm("add.rn.f32x2 %0, %1, %2;" : "=l"(d) : "l"(a), "l"(b));
    return d;
}
__device__ __forceinline__ ull pack2(float x, float y) {
    ull r; asm("mov.b64 %0, {%1, %2};" : "=l"(r) : "f"(x), "f"(y));
    return r;
}
__device__ __forceinline__ void unpack2(ull v, float& x, float& y) {
    asm("mov.b64 {%0, %1}, %2;" : "=f"(x), "=f"(y) : "l"(v));
}

// ---------------- k1: xw[s,b,h] = lookup[idx[s,b]] @ Wx ----------------
__global__ void k_embed_xw(const int* __restrict__ idx,
                           const float* __restrict__ lookup,
                           const float* __restrict__ wx) {
    __shared__ float sWx[E_ * H_];
    for (int i = threadIdx.x; i < E_ * H_; i += blockDim.x) sWx[i] = wx[i];
    __syncthreads();

    int r = blockIdx.x * blockDim.x + threadIdx.x;   // row = s*B + b
    int id = idx[r];
    float x[E_];
    const float4* lp = reinterpret_cast<const float4*>(lookup + (size_t)id * E_);
    #pragma unroll
    for (int i = 0; i < E_ / 4; i++) {
        float4 t = lp[i];
        x[4*i] = t.x; x[4*i+1] = t.y; x[4*i+2] = t.z; x[4*i+3] = t.w;
    }
    #pragma unroll
    for (int h = 0; h < H_; h++) {
        float a = 0.f;
        #pragma unroll
        for (int e = 0; e < E_; e++) a += x[e] * sWx[e * H_ + h];
        g_xw[r * H_ + h] = a;
    }
}

// ---------------- k2: sequential recurrence, single CTA ----------------
// thread tid = b*16 + j computes h_new[b][j] each step.
__global__ void k_rnn(const float* __restrict__ wh, const float* __restrict__ h0) {
    __shared__ float sWh[H_ * H_];
    __shared__ float sh[B_ * H_];
    int tid = threadIdx.x;                 // 1024 threads
    if (tid < H_ * H_) sWh[tid] = wh[tid];
    sh[tid] = h0[tid];
    __syncthreads();

    int b = tid >> 4, j = tid & 15;
    for (int s = 0; s < S_; s++) {
        float a = g_xw[s * (B_ * H_) + tid];
        #pragma unroll
        for (int k = 0; k < H_; k++) a += sh[b * H_ + k] * sWh[k * H_ + j];
        float hn = tanhf(a);
        __syncthreads();                   // all reads of sh done
        sh[tid] = hn;
        g_hdup[s * (B_ * H_) + tid] = pack2(hn, hn);
        __syncthreads();                   // sh stable for next step
    }
}

// ---------------- k3: partial sum of exp(logits) per row --------------
// CTA: 4 warps; warp handles 4 rows over one V-chunk; 4 rows x 4 v per thread.
__global__ __launch_bounds__(128, 2)
void k_lse_partial(const float* __restrict__ wo) {
    int lane = threadIdx.x & 31;
    int w    = threadIdx.x >> 5;
    int row0 = blockIdx.x * 16 + w * 4;
    int vbase = blockIdx.y * VCHUNK + lane * 4;

    ull h2[4][H_];
    #pragma unroll
    for (int r = 0; r < 4; r++)
        #pragma unroll
        for (int k = 0; k < H_; k++)
            h2[r][k] = g_hdup[(size_t)(row0 + r) * H_ + k];

    float s0 = 0.f, s1 = 0.f, s2 = 0.f, s3 = 0.f;
    const float* wp = wo + vbase;

    for (int it = 0; it < VCHUNK / 128; it++) {
        ull a00=0,a01=0,a10=0,a11=0,a20=0,a21=0,a30=0,a31=0;
        const float* wpi = wp + it * 128;
        #pragma unroll
        for (int k = 0; k < H_; k++) {
            ulonglong2 wv = *reinterpret_cast<const ulonglong2*>(wpi + (size_t)k * V_);
            a00 = ffma2(h2[0][k], wv.x, a00);  a01 = ffma2(h2[0][k], wv.y, a01);
            a10 = ffma2(h2[1][k], wv.x, a10);  a11 = ffma2(h2[1][k], wv.y, a11);
            a20 = ffma2(h2[2][k], wv.x, a20);  a21 = ffma2(h2[2][k], wv.y, a21);
            a30 = ffma2(h2[3][k], wv.x, a30);  a31 = ffma2(h2[3][k], wv.y, a31);
        }
        float x, y;
        unpack2(a00, x, y); s0 += __expf(x) + __expf(y);
        unpack2(a01, x, y); s0 += __expf(x) + __expf(y);
        unpack2(a10, x, y); s1 += __expf(x) + __expf(y);
        unpack2(a11, x, y); s1 += __expf(x) + __expf(y);
        unpack2(a20, x, y); s2 += __expf(x) + __expf(y);
        unpack2(a21, x, y); s2 += __expf(x) + __expf(y);
        unpack2(a30, x, y); s3 += __expf(x) + __expf(y);
        unpack2(a31, x, y); s3 += __expf(x) + __expf(y);
    }

    #pragma unroll
    for (int off = 16; off; off >>= 1) {
        s0 += __shfl_xor_sync(0xffffffffu, s0, off);
        s1 += __shfl_xor_sync(0xffffffffu, s1, off);
        s2 += __shfl_xor_sync(0xffffffffu, s2, off);
        s3 += __shfl_xor_sync(0xffffffffu, s3, off);
    }
    if (lane == 0) {
        float* p = g_part + blockIdx.y * ROWS + row0;
        p[0] = s0; p[1] = s1; p[2] = s2; p[3] = s3;
    }
}

// ---------------- k4: lse = log(sum of partials) ----------------------
__global__ void k_lse_final() {
    int r = blockIdx.x * blockDim.x + threadIdx.x;
    float s = 0.f;
    #pragma unroll
    for (int c = 0; c < NCHUNK; c++) s += g_part[c * ROWS + r];
    g_lse[r] = logf(s);
}

// ---------------- k5: out = logits - lse ------------------------------
__global__ __launch_bounds__(128, 2)
void k_out(const float* __restrict__ wo, float* __restrict__ out) {
    int lane = threadIdx.x & 31;
    int w    = threadIdx.x >> 5;
    int row0 = blockIdx.x * 16 + w * 4;
    int vbase = blockIdx.y * VCHUNK + lane * 4;

    ull h2[4][H_];
    #pragma unroll
    for (int r = 0; r < 4; r++)
        #pragma unroll
        for (int k = 0; k < H_; k++)
            h2[r][k] = g_hdup[(size_t)(row0 + r) * H_ + k];

    ull nl[4];
    #pragma unroll
    for (int r = 0; r < 4; r++) {
        float l = -g_lse[row0 + r];
        nl[r] = pack2(l, l);
    }

    const float* wp = wo + vbase;
    float* op = out + vbase;

    for (int it = 0; it < VCHUNK / 128; it++) {
        ull a00=0,a01=0,a10=0,a11=0,a20=0,a21=0,a30=0,a31=0;
        const float* wpi = wp + it * 128;
        #pragma unroll
        for (int k = 0; k < H_; k++) {
            ulonglong2 wv = *reinterpret_cast<const ulonglong2*>(wpi + (size_t)k * V_);
            a00 = ffma2(h2[0][k], wv.x, a00);  a01 = ffma2(h2[0][k], wv.y, a01);
            a10 = ffma2(h2[1][k], wv.x, a10);  a11 = ffma2(h2[1][k], wv.y, a11);
            a20 = ffma2(h2[2][k], wv.x, a20);  a21 = ffma2(h2[2][k], wv.y, a21);
            a30 = ffma2(h2[3][k], wv.x, a30);  a31 = ffma2(h2[3][k], wv.y, a31);
        }
        ulonglong2 st;
        float* opi = op + it * 128;
        st.x = fadd2(a00, nl[0]); st.y = fadd2(a01, nl[0]);
        *reinterpret_cast<ulonglong2*>(opi + (size_t)(row0 + 0) * V_) = st;
        st.x = fadd2(a10, nl[1]); st.y = fadd2(a11, nl[1]);
        *reinterpret_cast<ulonglong2*>(opi + (size_t)(row0 + 1) * V_) = st;
        st.x = fadd2(a20, nl[2]); st.y = fadd2(a21, nl[2]);
        *reinterpret_cast<ulonglong2*>(opi + (size_t)(row0 + 2) * V_) = st;
        st.x = fadd2(a30, nl[3]); st.y = fadd2(a31, nl[3]);
        *reinterpret_cast<ulonglong2*>(opi + (size_t)(row0 + 3) * V_) = st;
    }
}

// ---------------- launch --------------------------------------------------
extern "C" void kernel_launch(void* const* d_in, const int* in_sizes, int n_in,
                              void* d_out, int out_size) {
    const int*   idx    = (const int*)  d_in[0];   // input_batch [S,B]
    const float* lookup = (const float*)d_in[1];   // [V,E]
    const float* wx     = (const float*)d_in[2];   // [E,H]
    const float* wh     = (const float*)d_in[3];   // [H,H]
    const float* wo     = (const float*)d_in[4];   // [H,V]
    const float* h0     = (const float*)d_in[5];   // [B,H]
    float* out = (float*)d_out;                    // [S,B,V]

    k_embed_xw<<<ROWS / 128, 128>>>(idx, lookup, wx);
    k_rnn<<<1, B_ * H_>>>(wh, h0);
    k_lse_partial<<<dim3(ROWS / 16, NCHUNK), 128>>>(wo);
    k_lse_final<<<ROWS / 256, 256>>>();
    k_out<<<dim3(ROWS / 16, NCHUNK), 128>>>(wo, out);
}